// round 14
// baseline (speedup 1.0000x reference)
#include <cuda_runtime.h>
#include <cuda_fp16.h>
#include <math.h>
#include <stdint.h>

// ---------------- problem constants ----------------
#define NT 4096
#define NH 2048
#define NF 8192
#define NE 8

#define BM 128
#define KB 64                           // K elems per stage
#define NSLOT (2*NT)                    // 8192
#define MAX_TILES (NSLOT/BM + NE)       // 72
#define MAX_SLOTS (MAX_TILES*BM)        // 9216
#define NST1 (NH/KB)                    // 32
#define NST2 (NF/KB)                    // 128

#define TILE0   1024
// GEMM1: stage = A fp16 (128x64=16384) + B1 fp32 (64x288=18432) + B3 fp32
#define G1_BOFF 16384
#define G1_BSZ  18432
#define G1_STG  (G1_BOFF + 2*G1_BSZ)    // 53248
#define DSMEM1  (TILE0 + 2*G1_STG)      // 107520 -> 2 CTAs/SM
// GEMM2: 3 stages x (A 16KB + B 16KB)
#define SA      16384
#define G2_STG  32768
#define DSMEM2  (TILE0 + 3*G2_STG)      // 99328 -> 2 CTAs/SM

// ---------------- device scratch ----------------
__device__ int    g_tok_expert[NSLOT];
__device__ float  g_tok_weight[NSLOT];
__device__ int    g_slot_token[MAX_SLOTS];
__device__ float  g_slot_weight[MAX_SLOTS];
__device__ int    g_tile_expert[MAX_TILES];
__device__ __half g_hh[(size_t)MAX_SLOTS * NF];      // 151 MB
__device__ __half g_xh[(size_t)NT * NH];             // 16 MB
__device__ __half g_w2h[(size_t)NE * NH * NF];       // 268 MB

// ---------------- PTX helpers ----------------
__device__ __forceinline__ uint32_t s2u(const void* p) {
    uint32_t a;
    asm("{ .reg .u64 t; cvta.to.shared.u64 t, %1; cvt.u32.u64 %0, t; }" : "=r"(a) : "l"(p));
    return a;
}
#define CP16(dst, src, sz)                                                     \
    asm volatile("cp.async.cg.shared.global [%0], [%1], 16, %2;"               \
                 :: "r"(dst), "l"(src), "r"(sz))
#define CP_COMMIT() asm volatile("cp.async.commit_group;" ::: "memory")
#define CP_WAIT1()  asm volatile("cp.async.wait_group 1;" ::: "memory")

#define LDSM4(r, a)                                                            \
    asm volatile("ldmatrix.sync.aligned.m8n8.x4.shared.b16 {%0,%1,%2,%3}, [%4];" \
        : "=r"((r)[0]), "=r"((r)[1]), "=r"((r)[2]), "=r"((r)[3]) : "r"(a))

#define LDSF2(f, a)                                                            \
    asm volatile("ld.shared.v2.f32 {%0,%1}, [%2];" : "=f"((f).x), "=f"((f).y) : "r"(a))

__device__ __forceinline__ void mma16(float* d, const uint32_t* a, const uint32_t* b) {
    asm volatile(
        "mma.sync.aligned.m16n8k16.row.col.f32.f16.f16.f32 "
        "{%0,%1,%2,%3},{%4,%5,%6,%7},{%8,%9},{%0,%1,%2,%3};"
        : "+f"(d[0]), "+f"(d[1]), "+f"(d[2]), "+f"(d[3])
        : "r"(a[0]), "r"(a[1]), "r"(a[2]), "r"(a[3]), "r"(b[0]), "r"(b[1]));
}

__device__ __forceinline__ uint32_t h2u(__half2 h) {
    uint32_t u; asm("mov.b32 %0, %1;" : "=r"(u) : "r"(*(uint32_t*)&h)); return u;
}

__device__ __forceinline__ void cvt_store(const float4* src, __half2* dst, size_t i) {
    float4 v = src[i];
    dst[2 * i]     = __floats2half2_rn(v.x, v.y);
    dst[2 * i + 1] = __floats2half2_rn(v.z, v.w);
}

// ---------------- prep: zero out + cvt x, router interleaved ----------------
#define N4_OUT  ((size_t)NT * NH / 4)          // 2,097,152
#define N4_W    ((size_t)NE * NF * NH / 4)     // 33,554,432
#define PREP_BLOCKS (20480)                     // 4096 router + 16384 bulk

__global__ void k_prep(const float* __restrict__ x, const float* __restrict__ gw,
                       float* __restrict__ out) {
    const int tid = threadIdx.x;
    const unsigned bx = blockIdx.x;

    if (bx < 16384u && (bx & 3u) == 0u) {        // router blocks, every 4th
        const int t = (int)(bx >> 2);
        float acc[NE];
#pragma unroll
        for (int e = 0; e < NE; e++) acc[e] = 0.f;
        const float* xr = x + (size_t)t * NH;
        for (int h = tid; h < NH; h += 256) {
            float xv = xr[h];
#pragma unroll
            for (int e = 0; e < NE; e++) acc[e] += xv * gw[e * NH + h];
        }
        __shared__ float part[NE][256];
#pragma unroll
        for (int e = 0; e < NE; e++) part[e][tid] = acc[e];
        __syncthreads();
        if (tid < NE) {
            float s = 0.f;
            for (int i = 0; i < 256; i++) s += part[tid][i];
            part[tid][0] = s;
        }
        __syncthreads();
        if (tid == 0) {
            float l[NE];
#pragma unroll
            for (int e = 0; e < NE; e++) l[e] = part[e][0];
            int i0 = 0;
#pragma unroll
            for (int e = 1; e < NE; e++) if (l[e] > l[i0]) i0 = e;
            int i1 = -1;
#pragma unroll
            for (int e = 0; e < NE; e++)
                if (e != i0 && (i1 < 0 || l[e] > l[i1])) i1 = e;
            float w0 = 1.f / (1.f + expf(l[i1] - l[i0]));
            g_tok_expert[2 * t] = i0;  g_tok_expert[2 * t + 1] = i1;
            g_tok_weight[2 * t] = w0;  g_tok_weight[2 * t + 1] = 1.f - w0;
        }
        return;
    }

    unsigned bulk = (bx < 16384u) ? (bx - (bx >> 2) - 1u) : (bx - 4096u);
    size_t i = (size_t)bulk * 256 + tid;
    if (i < N4_OUT) {
        ((float4*)out)[i] = make_float4(0.f, 0.f, 0.f, 0.f);
        return;
    }
    i -= N4_OUT;
    if (i < N4_OUT) cvt_store((const float4*)x, (__half2*)g_xh, i);
}

// ---------------- finalize: counts -> offsets -> tile map -> slots ----------------
__global__ void k_finalize() {
    const int tid = threadIdx.x;
    __shared__ int cnt[NE], off[NE + 1], cur[NE];
    if (tid < NE) { cnt[tid] = 0; cur[tid] = 0; }
    __syncthreads();
    for (int i = tid; i < NSLOT; i += 256) atomicAdd(&cnt[g_tok_expert[i]], 1);
    __syncthreads();
    if (tid == 0) {
        int o = 0;
        for (int e = 0; e < NE; e++) {
            off[e] = o;
            o += ((cnt[e] + BM - 1) / BM) * BM;
        }
        off[NE] = o;
    }
    __syncthreads();
    const int ntiles = off[NE] / BM;
    for (int i = tid; i < MAX_TILES; i += 256) {
        int ex = -1;
        if (i < ntiles) {
            int r = i * BM;
            for (int e = 0; e < NE; e++)
                if (r >= off[e] && r < off[e + 1]) ex = e;
        }
        g_tile_expert[i] = ex;
    }
    for (int i = tid; i < MAX_SLOTS; i += 256) {
        g_slot_token[i]  = -1;
        g_slot_weight[i] = 0.f;
    }
    __syncthreads();
    for (int i = tid; i < NSLOT; i += 256) {
        int e = g_tok_expert[i];
        int pos = atomicAdd(&cur[e], 1);
        int s = off[e] + pos;
        g_slot_token[s]  = i >> 1;
        g_slot_weight[s] = g_tok_weight[i];
    }
}

// ---------------- GEMM1: direct fp32 B, tile 128 x 64 per mat, 2 CTAs/SM ----------------
// grid (x=72, y=144). y%9==8 -> w2 cvt slice; else fblk = y - y/9 (0..127).
__global__ void __launch_bounds__(256, 2)
k_gemm1(const float* __restrict__ w1src, const float* __restrict__ w3src,
        const float* __restrict__ w2src) {
    const int tid = threadIdx.x;
    const int y = blockIdx.y;

    if (y % 9 == 8) {                   // --- w2 fp32->fp16 conversion slice ---
        const size_t lin   = ((size_t)(y / 9) * MAX_TILES + blockIdx.x) * 256 + tid;
        const size_t strid = (size_t)16 * MAX_TILES * 256;
        const float4* src = (const float4*)w2src;
        __half2* dst = (__half2*)g_w2h;
        for (size_t i = lin; i < N4_W; i += strid) cvt_store(src, dst, i);
        return;
    }

    const int e = g_tile_expert[blockIdx.x];
    if (e < 0) return;
    extern __shared__ char smem[];
    const uint32_t sb = s2u(smem);
    const int lane = tid & 31, wid = tid >> 5;
    const int fblk = y - y / 9;                       // 0..127
    const int r0 = blockIdx.x * BM, f0 = fblk * 64;

    int* toks = (int*)smem;
    if (tid < BM) toks[tid] = g_slot_token[r0 + tid];
    __syncthreads();

    // A loader: 4 chunks/thr (128 rows x 8 chunks of 8 halves, XOR swizzle)
    const __half* srcA[4]; uint32_t dstA[4], szA[4];
#pragma unroll
    for (int i = 0; i < 4; i++) {
        int idx = tid + 256 * i, row = idx >> 3, q = idx & 7;
        int t = toks[row];
        szA[i]  = (t >= 0) ? 16u : 0u;
        srcA[i] = g_xh + (size_t)(t >= 0 ? t : 0) * NH + q * 8;
        dstA[i] = sb + TILE0 + row * 128 + ((q ^ (row & 7)) << 4);
    }
    // B loader: fp32, 64 rows x 16 chunks (256B data, 288B padded rows); 4/thr/mat
    const float* w1b = w1src + ((size_t)e * NF + f0) * NH;
    const float* w3b = w3src + ((size_t)e * NF + f0) * NH;
    int  bOff[4]; uint32_t dstB[4];
#pragma unroll
    for (int i = 0; i < 4; i++) {
        int idx = tid + 256 * i, row = idx >> 4, c = idx & 15;
        bOff[i] = row * NH + c * 4;                  // element offset
        dstB[i] = sb + TILE0 + G1_BOFF + row * 288 + c * 16;
    }

#define G1_ISSUE(S) do {                                                       \
        uint32_t _o = ((S) & 1) * G1_STG; int _k = (S) * KB;                   \
        _Pragma("unroll") for (int i = 0; i < 4; i++)                          \
            CP16(dstA[i] + _o, srcA[i] + _k, szA[i]);                          \
        _Pragma("unroll") for (int i = 0; i < 4; i++)                          \
            CP16(dstB[i] + _o, w1b + bOff[i] + _k, 16u);                       \
        _Pragma("unroll") for (int i = 0; i < 4; i++)                          \
            CP16(dstB[i] + _o + G1_BSZ, w3b + bOff[i] + _k, 16u);              \
        CP_COMMIT();                                                           \
    } while (0)

    G1_ISSUE(0); G1_ISSUE(1);

    // 4 warps per mat in 2m x 2n; warp tile 64x32
    const int mat = wid >> 2, wm = (wid >> 1) & 1, wn = wid & 1;
    uint32_t mOff[4], swzA[4];
#pragma unroll
    for (int mf = 0; mf < 4; mf++) mOff[mf] = (wm * 64 + mf * 16 + (lane & 15)) * 128;
#pragma unroll
    for (int ks = 0; ks < 4; ks++)
        swzA[ks] = ((2 * ks + (lane >> 4)) ^ (lane & 7)) << 4;
    // B fragment base: n = wn*32 + nf*8 + lane/4 ; k0 = (lane%4)*2
    const uint32_t bFragBase = G1_BOFF + mat * G1_BSZ +
                               (uint32_t)(wn * 32 + (lane >> 2)) * 288 + (lane & 3) * 8;

    float acc[4][4][4] = {};

    for (int s = 0; s < NST1; s++) {
        CP_WAIT1();
        __syncthreads();
        const uint32_t aB = sb + TILE0 + (s & 1) * G1_STG;
        const uint32_t bB = aB + bFragBase;
#pragma unroll
        for (int ks = 0; ks < 4; ks++) {
            uint32_t a[4][4];
#pragma unroll
            for (int mf = 0; mf < 4; mf++) LDSM4(a[mf], aB + mOff[mf] + swzA[ks]);
            uint32_t breg[4][2];
#pragma unroll
            for (int nf = 0; nf < 4; nf++) {
                float2 lo, hi;
                uint32_t ba = bB + ks * 64 + nf * 2304;
                LDSF2(lo, ba);
                LDSF2(hi, ba + 32);
                breg[nf][0] = h2u(__floats2half2_rn(lo.x, lo.y));
                breg[nf][1] = h2u(__floats2half2_rn(hi.x, hi.y));
            }
#pragma unroll
            for (int mf = 0; mf < 4; mf++)
#pragma unroll
                for (int nf = 0; nf < 4; nf++)
                    mma16(acc[mf][nf], a[mf], breg[nf]);
        }
        __syncthreads();
        if (s + 2 < NST1) G1_ISSUE(s + 2); else CP_COMMIT();
    }

    // epilogue: planes 128x64 f32 per mat, SwiGLU fuse, fp16 store
    float* Sg = (float*)(smem + TILE0 + mat * 32768);
    const int rb = wm * 64, cb = wn * 32;
#pragma unroll
    for (int mf = 0; mf < 4; mf++)
#pragma unroll
        for (int nf = 0; nf < 4; nf++) {
            int r = rb + mf * 16 + (lane >> 2), c = cb + nf * 8 + (lane & 3) * 2;
            Sg[r * 64 + c]           = acc[mf][nf][0];
            Sg[r * 64 + c + 1]       = acc[mf][nf][1];
            Sg[(r + 8) * 64 + c]     = acc[mf][nf][2];
            Sg[(r + 8) * 64 + c + 1] = acc[mf][nf][3];
        }
    __syncthreads();
    const float4* S1 = (const float4*)(smem + TILE0);
    const float4* S3 = (const float4*)(smem + TILE0 + 32768);
#pragma unroll
    for (int k2 = 0; k2 < 8; k2++) {
        int i4 = tid + 256 * k2;
        int row = i4 >> 4, c4 = i4 & 15;
        float4 a = S1[i4], g = S3[i4];
        __half2 lo = __floats2half2_rn(a.x / (1.f + __expf(-a.x)) * g.x,
                                       a.y / (1.f + __expf(-a.y)) * g.y);
        __half2 hi = __floats2half2_rn(a.z / (1.f + __expf(-a.z)) * g.z,
                                       a.w / (1.f + __expf(-a.w)) * g.w);
        __half2* hp = (__half2*)(g_hh + (size_t)(r0 + row) * NF + f0 + c4 * 4);
        hp[0] = lo; hp[1] = hi;
    }
#undef G1_ISSUE
}

// ---------------- GEMM2: tile 128 x 128, 2 CTAs/SM (R13 proven) ----------------
__global__ void __launch_bounds__(256, 2)
k_gemm2(float* __restrict__ out) {
    const int e = g_tile_expert[blockIdx.x];
    if (e < 0) return;
    extern __shared__ char smem[];
    const uint32_t sb = s2u(smem);
    const int tid = threadIdx.x, lane = tid & 31, wid = tid >> 5;
    const int r0 = blockIdx.x * BM, h0 = blockIdx.y * 128;

    int*   toks = (int*)smem;
    float* wgts = (float*)(smem + 512);
    if (tid < BM) {
        toks[tid] = g_slot_token[r0 + tid];
        wgts[tid] = g_slot_weight[r0 + tid];
    }
    __syncthreads();

    const __half* srcA[4]; uint32_t dstA[4];
    const __half* srcB[4]; uint32_t dstB[4];
#pragma unroll
    for (int i = 0; i < 4; i++) {
        int idx = tid + 256 * i, row = idx >> 3, q = idx & 7;
        srcA[i] = g_hh + (size_t)(r0 + row) * NF + q * 8;
        srcB[i] = g_w2h + ((size_t)e * NH + h0 + row) * NF + q * 8;
        uint32_t sw = row * 128 + ((q ^ (row & 7)) << 4);
        dstA[i] = sb + TILE0 + sw;
        dstB[i] = sb + TILE0 + SA + sw;
    }

#define G2_ISSUE(S) do {                                                       \
        uint32_t _o = ((S) % 3) * G2_STG; int _k = (S) * KB;                   \
        _Pragma("unroll") for (int i = 0; i < 4; i++)                          \
            CP16(dstA[i] + _o, srcA[i] + _k, 16u);                             \
        _Pragma("unroll") for (int i = 0; i < 4; i++)                          \
            CP16(dstB[i] + _o, srcB[i] + _k, 16u);                             \
        CP_COMMIT();                                                           \
    } while (0)

    G2_ISSUE(0); G2_ISSUE(1);

    const int wm = wid >> 2, wn = wid & 3;
    uint32_t mOff[4], nOff[2], swzA[4], swzB[4];
#pragma unroll
    for (int mf = 0; mf < 4; mf++) mOff[mf] = (wm * 64 + mf * 16 + (lane & 15)) * 128;
#pragma unroll
    for (int np = 0; np < 2; np++)
        nOff[np] = (wn * 32 + np * 16 + ((lane >> 4) << 3) + (lane & 7)) * 128;
#pragma unroll
    for (int ks = 0; ks < 4; ks++) {
        swzA[ks] = ((2 * ks + (lane >> 4)) ^ (lane & 7)) << 4;
        swzB[ks] = ((2 * ks + ((lane >> 3) & 1)) ^ (lane & 7)) << 4;
    }

    float acc[4][4][4] = {};

    for (int s = 0; s < NST2; s++) {
        CP_WAIT1();
        __syncthreads();
        if (s + 2 < NST2) G2_ISSUE(s + 2); else CP_COMMIT();
        const uint32_t aB = sb + TILE0 + (s % 3) * G2_STG;
        const uint32_t bB = aB + SA;
#pragma unroll
        for (int ks = 0; ks < 4; ks++) {
            uint32_t a[4][4], b[2][4];
#pragma unroll
            for (int mf = 0; mf < 4; mf++) LDSM4(a[mf], aB + mOff[mf] + swzA[ks]);
#pragma unroll
            for (int np = 0; np < 2; np++) LDSM4(b[np], bB + nOff[np] + swzB[ks]);
#pragma unroll
            for (int mf = 0; mf < 4; mf++)
#pragma unroll
                for (int nf = 0; nf < 4; nf++)
                    mma16(acc[mf][nf], a[mf], &b[nf >> 1][(nf & 1) * 2]);
        }
        __syncthreads();
    }

    const int rb = wm * 64, cb = wn * 32;
#pragma unroll
    for (int mf = 0; mf < 4; mf++)
#pragma unroll
        for (int nf = 0; nf < 4; nf++) {
            int r = rb + mf * 16 + (lane >> 2), c = cb + nf * 8 + (lane & 3) * 2;
            int t0 = toks[r];
            if (t0 >= 0) {
                float w = wgts[r];
                float* op = out + (size_t)t0 * NH + h0 + c;
                atomicAdd(op,     w * acc[mf][nf][0]);
                atomicAdd(op + 1, w * acc[mf][nf][1]);
            }
            int t1 = toks[r + 8];
            if (t1 >= 0) {
                float w = wgts[r + 8];
                float* op = out + (size_t)t1 * NH + h0 + c;
                atomicAdd(op,     w * acc[mf][nf][2]);
                atomicAdd(op + 1, w * acc[mf][nf][3]);
            }
        }
#undef G2_ISSUE
}

// ---------------- launch ----------------
extern "C" void kernel_launch(void* const* d_in, const int* in_sizes, int n_in,
                              void* d_out, int out_size) {
    const float* x  = (const float*)d_in[0];
    const float* gw = (const float*)d_in[1];
    const float* w1 = (const float*)d_in[2];
    const float* w2 = (const float*)d_in[3];
    const float* w3 = (const float*)d_in[4];
    float* out = (float*)d_out;

    static int configured = 0;
    if (!configured) {
        cudaFuncSetAttribute(k_gemm1, cudaFuncAttributeMaxDynamicSharedMemorySize, DSMEM1);
        cudaFuncSetAttribute(k_gemm2, cudaFuncAttributeMaxDynamicSharedMemorySize, DSMEM2);
        configured = 1;
    }

    k_prep<<<PREP_BLOCKS, 256>>>(x, gw, out);
    k_finalize<<<1, 256>>>();
    k_gemm1<<<dim3(MAX_TILES, 144), 256, DSMEM1>>>(w1, w3, w2);
    k_gemm2<<<dim3(MAX_TILES, NH / 128), 256, DSMEM2>>>(out);
}

// round 15
// speedup vs baseline: 1.1066x; 1.1066x over previous
#include <cuda_runtime.h>
#include <cuda_fp16.h>
#include <math.h>
#include <stdint.h>

// ---------------- problem constants ----------------
#define NT 4096
#define NH 2048
#define NF 8192
#define NE 8

#define BM 128
#define KB 64                           // K halves per stage (128B rows)
#define NSLOT (2*NT)                    // 8192
#define MAX_TILES (NSLOT/BM + NE)       // 72
#define MAX_SLOTS (MAX_TILES*BM)        // 9216
#define NST1 (NH/KB)                    // 32
#define NST2 (NF/KB)                    // 128

// smem: toks/wgts in [0,1024); 3 stages x 32KB (R13 proven)
#define TILE0   1024
#define SA      16384                   // A tile 128x64 fp16
#define SB1     8192                    // gemm1 B tile 64x64 fp16 (per matrix)
#define STRIDE  32768
#define DSMEM   (TILE0 + 3*STRIDE)      // 99328 -> 2 CTAs/SM

// ---------------- device scratch ----------------
__device__ int    g_tok_expert[NSLOT];
__device__ float  g_tok_weight[NSLOT];
__device__ int    g_slot_token[MAX_SLOTS];
__device__ float  g_slot_weight[MAX_SLOTS];
__device__ int    g_tile_expert[MAX_TILES];
__device__ __half g_hh[(size_t)MAX_SLOTS * NF];      // 151 MB
__device__ __half g_xh[(size_t)NT * NH];             // 16 MB
__device__ __half g_w1h[(size_t)NE * NF * NH];       // 268 MB
__device__ __half g_w3h[(size_t)NE * NF * NH];       // 268 MB
__device__ __half g_w2h[(size_t)NE * NH * NF];       // 268 MB

// ---------------- PTX helpers ----------------
__device__ __forceinline__ uint32_t s2u(const void* p) {
    uint32_t a;
    asm("{ .reg .u64 t; cvta.to.shared.u64 t, %1; cvt.u32.u64 %0, t; }" : "=r"(a) : "l"(p));
    return a;
}
#define CP16(dst, src, sz)                                                     \
    asm volatile("cp.async.cg.shared.global [%0], [%1], 16, %2;"               \
                 :: "r"(dst), "l"(src), "r"(sz))
#define CP_COMMIT() asm volatile("cp.async.commit_group;" ::: "memory")
#define CP_WAIT1()  asm volatile("cp.async.wait_group 1;" ::: "memory")

#define LDSM4(r, a)                                                            \
    asm volatile("ldmatrix.sync.aligned.m8n8.x4.shared.b16 {%0,%1,%2,%3}, [%4];" \
        : "=r"((r)[0]), "=r"((r)[1]), "=r"((r)[2]), "=r"((r)[3]) : "r"(a))

__device__ __forceinline__ void mma16(float* d, const uint32_t* a, const uint32_t* b) {
    asm volatile(
        "mma.sync.aligned.m16n8k16.row.col.f32.f16.f16.f32 "
        "{%0,%1,%2,%3},{%4,%5,%6,%7},{%8,%9},{%0,%1,%2,%3};"
        : "+f"(d[0]), "+f"(d[1]), "+f"(d[2]), "+f"(d[3])
        : "r"(a[0]), "r"(a[1]), "r"(a[2]), "r"(a[3]), "r"(b[0]), "r"(b[1]));
}

__device__ __forceinline__ void cvt_store(const float4* src, __half2* dst, size_t i) {
    float4 v = src[i];
    dst[2 * i]     = __floats2half2_rn(v.x, v.y);
    dst[2 * i + 1] = __floats2half2_rn(v.z, v.w);
}

// ---------------- sizes ----------------
#define N4_OUT  ((size_t)NT * NH / 4)          // 2,097,152 float4
#define N4_W    ((size_t)NE * NF * NH / 4)     // 33,554,432 float4 (per weight)
#define HALF4   ((size_t)NF * NH / 8)          // 2,097,152 float4 (half expert)
#define N4_WH   (N4_W / 2)                     // 16,777,216 (lower/upper half)

// prep: zero + x cvt + w1/w3 LOWER halves; router interleaved every 37th block
// bulk total = 2*N4_OUT + 2*N4_WH = 37,748,736 /256 = 147,456 blocks; +4096 router
#define PREP_BLOCKS 151552u

__global__ void k_prep(const float* __restrict__ x, const float* __restrict__ gw,
                       const float* __restrict__ w1, const float* __restrict__ w3,
                       float* __restrict__ out) {
    const int tid = threadIdx.x;
    const unsigned bx = blockIdx.x;

    if (bx % 37u == 0u) {                        // router block (t = bx/37 < 4096)
        const int t = (int)(bx / 37u);
        float acc[NE];
#pragma unroll
        for (int e = 0; e < NE; e++) acc[e] = 0.f;
        const float* xr = x + (size_t)t * NH;
        for (int h = tid; h < NH; h += 256) {
            float xv = xr[h];
#pragma unroll
            for (int e = 0; e < NE; e++) acc[e] += xv * gw[e * NH + h];
        }
        __shared__ float part[NE][256];
#pragma unroll
        for (int e = 0; e < NE; e++) part[e][tid] = acc[e];
        __syncthreads();
        if (tid < NE) {
            float s = 0.f;
            for (int i = 0; i < 256; i++) s += part[tid][i];
            part[tid][0] = s;
        }
        __syncthreads();
        if (tid == 0) {
            float l[NE];
#pragma unroll
            for (int e = 0; e < NE; e++) l[e] = part[e][0];
            int i0 = 0;
#pragma unroll
            for (int e = 1; e < NE; e++) if (l[e] > l[i0]) i0 = e;
            int i1 = -1;
#pragma unroll
            for (int e = 0; e < NE; e++)
                if (e != i0 && (i1 < 0 || l[e] > l[i1])) i1 = e;
            float w0 = 1.f / (1.f + expf(l[i1] - l[i0]));
            g_tok_expert[2 * t] = i0;  g_tok_expert[2 * t + 1] = i1;
            g_tok_weight[2 * t] = w0;  g_tok_weight[2 * t + 1] = 1.f - w0;
        }
        return;
    }

    const unsigned bulk = bx - (bx / 37u) - 1u;
    size_t i = (size_t)bulk * 256 + tid;
    if (i < N4_OUT) {
        ((float4*)out)[i] = make_float4(0.f, 0.f, 0.f, 0.f);
        return;
    }
    i -= N4_OUT;
    if (i < N4_OUT) { cvt_store((const float4*)x, (__half2*)g_xh, i); return; }
    i -= N4_OUT;
    if (i < N4_WH) {                             // w1 lower half (per expert)
        size_t e = i >> 21, off = i & (HALF4 - 1);
        size_t idx = (e << 22) + off;
        cvt_store((const float4*)w1, (__half2*)g_w1h, idx);
        return;
    }
    i -= N4_WH;
    if (i < N4_WH) {                             // w3 lower half
        size_t e = i >> 21, off = i & (HALF4 - 1);
        size_t idx = (e << 22) + off;
        cvt_store((const float4*)w3, (__half2*)g_w3h, idx);
    }
}

// ---------------- finalize: counts -> offsets -> tile map -> slots ----------------
__global__ void k_finalize() {
    const int tid = threadIdx.x;
    __shared__ int cnt[NE], off[NE + 1], cur[NE];
    if (tid < NE) { cnt[tid] = 0; cur[tid] = 0; }
    __syncthreads();
    for (int i = tid; i < NSLOT; i += 256) atomicAdd(&cnt[g_tok_expert[i]], 1);
    __syncthreads();
    if (tid == 0) {
        int o = 0;
        for (int e = 0; e < NE; e++) {
            off[e] = o;
            o += ((cnt[e] + BM - 1) / BM) * BM;
        }
        off[NE] = o;
    }
    __syncthreads();
    const int ntiles = off[NE] / BM;
    for (int i = tid; i < MAX_TILES; i += 256) {
        int ex = -1;
        if (i < ntiles) {
            int r = i * BM;
            for (int e = 0; e < NE; e++)
                if (r >= off[e] && r < off[e + 1]) ex = e;
        }
        g_tile_expert[i] = ex;
    }
    for (int i = tid; i < MAX_SLOTS; i += 256) {
        g_slot_token[i]  = -1;
        g_slot_weight[i] = 0.f;
    }
    __syncthreads();
    for (int i = tid; i < NSLOT; i += 256) {
        int e = g_tok_expert[i];
        int pos = atomicAdd(&cur[e], 1);
        int s = off[e] + pos;
        g_slot_token[s]  = i >> 1;
        g_slot_weight[s] = g_tok_weight[i];
    }
}

// ---------------- GEMM1 (R13 core), launched twice with fhalf = 0 / 1 ----------------
// grid (x=72, y=72). y%9==8 -> cvt slice:
//   fhalf==0: convert w1/w3 UPPER halves (needed by the NEXT launch)
//   fhalf==1: convert w2 (needed by gemm2)
// else fblk = fhalf*64 + (y - y/9), f0 = fblk*64.
__global__ void __launch_bounds__(256, 2)
k_gemm1(const float* __restrict__ w1src, const float* __restrict__ w3src,
        const float* __restrict__ w2src, int fhalf) {
    const int tid = threadIdx.x;
    const int y = blockIdx.y;

    if (y % 9 == 8) {
        const size_t lin   = ((size_t)(y / 9) * MAX_TILES + blockIdx.x) * 256 + tid;
        const size_t strid = (size_t)8 * MAX_TILES * 256;        // 147,456
        if (fhalf == 0) {
            for (size_t j = lin; j < N4_WH; j += strid) {
                size_t e = j >> 21, off = j & (HALF4 - 1);
                size_t idx = (e << 22) + HALF4 + off;            // upper half
                cvt_store((const float4*)w1src, (__half2*)g_w1h, idx);
                cvt_store((const float4*)w3src, (__half2*)g_w3h, idx);
            }
        } else {
            for (size_t j = lin; j < N4_W; j += strid)
                cvt_store((const float4*)w2src, (__half2*)g_w2h, j);
        }
        return;
    }

    const int e = g_tile_expert[blockIdx.x];
    if (e < 0) return;
    extern __shared__ char smem[];
    const uint32_t sb = s2u(smem);
    const int lane = tid & 31, wid = tid >> 5;
    const int fblk = fhalf * 64 + (y - y / 9);        // 0..127
    const int r0 = blockIdx.x * BM, f0 = fblk * 64;

    int* toks = (int*)smem;
    if (tid < BM) toks[tid] = g_slot_token[r0 + tid];
    __syncthreads();

    const __half* srcA[4]; uint32_t dstA[4], szA[4];
    const __half* srcB1[2]; const __half* srcB3[2]; uint32_t dstB[2];
#pragma unroll
    for (int i = 0; i < 4; i++) {
        int idx = tid + 256 * i, row = idx >> 3, q = idx & 7;
        int t = toks[row];
        szA[i]  = (t >= 0) ? 16u : 0u;
        srcA[i] = g_xh + (size_t)(t >= 0 ? t : 0) * NH + q * 8;
        dstA[i] = sb + TILE0 + row * 128 + ((q ^ (row & 7)) << 4);
    }
#pragma unroll
    for (int i = 0; i < 2; i++) {
        int idx = tid + 256 * i, row = idx >> 3, q = idx & 7;   // row 0..63
        srcB1[i] = g_w1h + ((size_t)e * NF + f0 + row) * NH + q * 8;
        srcB3[i] = g_w3h + ((size_t)e * NF + f0 + row) * NH + q * 8;
        dstB[i]  = sb + TILE0 + SA + row * 128 + ((q ^ (row & 7)) << 4);
    }

#define G1_ISSUE(S) do {                                                       \
        uint32_t _o = ((S) % 3) * STRIDE; int _k = (S) * KB;                   \
        _Pragma("unroll") for (int i = 0; i < 4; i++)                          \
            CP16(dstA[i] + _o, srcA[i] + _k, szA[i]);                          \
        _Pragma("unroll") for (int i = 0; i < 2; i++)                          \
            CP16(dstB[i] + _o, srcB1[i] + _k, 16u);                            \
        _Pragma("unroll") for (int i = 0; i < 2; i++)                          \
            CP16(dstB[i] + _o + SB1, srcB3[i] + _k, 16u);                      \
        CP_COMMIT();                                                           \
    } while (0)

    G1_ISSUE(0); G1_ISSUE(1);

    const int mat = wid >> 2, wm = (wid >> 1) & 1, wn = wid & 1;
    uint32_t mOff[4], nOff[2], swzA[4], swzB[4];
#pragma unroll
    for (int mf = 0; mf < 4; mf++) mOff[mf] = (wm * 64 + mf * 16 + (lane & 15)) * 128;
#pragma unroll
    for (int np = 0; np < 2; np++)
        nOff[np] = (wn * 32 + np * 16 + ((lane >> 4) << 3) + (lane & 7)) * 128;
#pragma unroll
    for (int ks = 0; ks < 4; ks++) {
        swzA[ks] = ((2 * ks + (lane >> 4)) ^ (lane & 7)) << 4;
        swzB[ks] = ((2 * ks + ((lane >> 3) & 1)) ^ (lane & 7)) << 4;
    }

    float acc[4][4][4] = {};

    for (int s = 0; s < NST1; s++) {
        CP_WAIT1();
        __syncthreads();
        if (s + 2 < NST1) G1_ISSUE(s + 2); else CP_COMMIT();
        const uint32_t aB = sb + TILE0 + (s % 3) * STRIDE;
        const uint32_t bB = aB + SA + mat * SB1;
#pragma unroll
        for (int ks = 0; ks < 4; ks++) {
            uint32_t a[4][4], b[2][4];
#pragma unroll
            for (int mf = 0; mf < 4; mf++) LDSM4(a[mf], aB + mOff[mf] + swzA[ks]);
#pragma unroll
            for (int np = 0; np < 2; np++) LDSM4(b[np], bB + nOff[np] + swzB[ks]);
#pragma unroll
            for (int mf = 0; mf < 4; mf++)
#pragma unroll
                for (int nf = 0; nf < 4; nf++)
                    mma16(acc[mf][nf], a[mf], &b[nf >> 1][(nf & 1) * 2]);
        }
        __syncthreads();
    }

    float* Sg = (float*)(smem + TILE0 + mat * 32768);
    const int rb = wm * 64, cb = wn * 32;
#pragma unroll
    for (int mf = 0; mf < 4; mf++)
#pragma unroll
        for (int nf = 0; nf < 4; nf++) {
            int r = rb + mf * 16 + (lane >> 2), c = cb + nf * 8 + (lane & 3) * 2;
            Sg[r * 64 + c]           = acc[mf][nf][0];
            Sg[r * 64 + c + 1]       = acc[mf][nf][1];
            Sg[(r + 8) * 64 + c]     = acc[mf][nf][2];
            Sg[(r + 8) * 64 + c + 1] = acc[mf][nf][3];
        }
    __syncthreads();
    const float4* S1 = (const float4*)(smem + TILE0);
    const float4* S3 = (const float4*)(smem + TILE0 + 32768);
#pragma unroll
    for (int k2 = 0; k2 < 8; k2++) {
        int i4 = tid + 256 * k2;
        int row = i4 >> 4, c4 = i4 & 15;
        float4 a = S1[i4], g = S3[i4];
        __half2 lo = __floats2half2_rn(a.x / (1.f + __expf(-a.x)) * g.x,
                                       a.y / (1.f + __expf(-a.y)) * g.y);
        __half2 hi = __floats2half2_rn(a.z / (1.f + __expf(-a.z)) * g.z,
                                       a.w / (1.f + __expf(-a.w)) * g.w);
        __half2* hp = (__half2*)(g_hh + (size_t)(r0 + row) * NF + f0 + c4 * 4);
        hp[0] = lo; hp[1] = hi;
    }
#undef G1_ISSUE
}

// ---------------- GEMM2: tile 128 x 128, 2 CTAs/SM (R13 verbatim) ----------------
__global__ void __launch_bounds__(256, 2)
k_gemm2(float* __restrict__ out) {
    const int e = g_tile_expert[blockIdx.x];
    if (e < 0) return;
    extern __shared__ char smem[];
    const uint32_t sb = s2u(smem);
    const int tid = threadIdx.x, lane = tid & 31, wid = tid >> 5;
    const int r0 = blockIdx.x * BM, h0 = blockIdx.y * 128;

    int*   toks = (int*)smem;
    float* wgts = (float*)(smem + 512);
    if (tid < BM) {
        toks[tid] = g_slot_token[r0 + tid];
        wgts[tid] = g_slot_weight[r0 + tid];
    }
    __syncthreads();

    const __half* srcA[4]; uint32_t dstA[4];
    const __half* srcB[4]; uint32_t dstB[4];
#pragma unroll
    for (int i = 0; i < 4; i++) {
        int idx = tid + 256 * i, row = idx >> 3, q = idx & 7;
        srcA[i] = g_hh + (size_t)(r0 + row) * NF + q * 8;
        srcB[i] = g_w2h + ((size_t)e * NH + h0 + row) * NF + q * 8;
        uint32_t sw = row * 128 + ((q ^ (row & 7)) << 4);
        dstA[i] = sb + TILE0 + sw;
        dstB[i] = sb + TILE0 + SA + sw;
    }

#define G2_ISSUE(S) do {                                                       \
        uint32_t _o = ((S) % 3) * STRIDE; int _k = (S) * KB;                   \
        _Pragma("unroll") for (int i = 0; i < 4; i++)                          \
            CP16(dstA[i] + _o, srcA[i] + _k, 16u);                             \
        _Pragma("unroll") for (int i = 0; i < 4; i++)                          \
            CP16(dstB[i] + _o, srcB[i] + _k, 16u);                             \
        CP_COMMIT();                                                           \
    } while (0)

    G2_ISSUE(0); G2_ISSUE(1);

    const int wm = wid >> 2, wn = wid & 3;
    uint32_t mOff[4], nOff[2], swzA[4], swzB[4];
#pragma unroll
    for (int mf = 0; mf < 4; mf++) mOff[mf] = (wm * 64 + mf * 16 + (lane & 15)) * 128;
#pragma unroll
    for (int np = 0; np < 2; np++)
        nOff[np] = (wn * 32 + np * 16 + ((lane >> 4) << 3) + (lane & 7)) * 128;
#pragma unroll
    for (int ks = 0; ks < 4; ks++) {
        swzA[ks] = ((2 * ks + (lane >> 4)) ^ (lane & 7)) << 4;
        swzB[ks] = ((2 * ks + ((lane >> 3) & 1)) ^ (lane & 7)) << 4;
    }

    float acc[4][4][4] = {};

    for (int s = 0; s < NST2; s++) {
        CP_WAIT1();
        __syncthreads();
        if (s + 2 < NST2) G2_ISSUE(s + 2); else CP_COMMIT();
        const uint32_t aB = sb + TILE0 + (s % 3) * STRIDE;
        const uint32_t bB = aB + SA;
#pragma unroll
        for (int ks = 0; ks < 4; ks++) {
            uint32_t a[4][4], b[2][4];
#pragma unroll
            for (int mf = 0; mf < 4; mf++) LDSM4(a[mf], aB + mOff[mf] + swzA[ks]);
#pragma unroll
            for (int np = 0; np < 2; np++) LDSM4(b[np], bB + nOff[np] + swzB[ks]);
#pragma unroll
            for (int mf = 0; mf < 4; mf++)
#pragma unroll
                for (int nf = 0; nf < 4; nf++)
                    mma16(acc[mf][nf], a[mf], &b[nf >> 1][(nf & 1) * 2]);
        }
        __syncthreads();
    }

    const int rb = wm * 64, cb = wn * 32;
#pragma unroll
    for (int mf = 0; mf < 4; mf++)
#pragma unroll
        for (int nf = 0; nf < 4; nf++) {
            int r = rb + mf * 16 + (lane >> 2), c = cb + nf * 8 + (lane & 3) * 2;
            int t0 = toks[r];
            if (t0 >= 0) {
                float w = wgts[r];
                float* op = out + (size_t)t0 * NH + h0 + c;
                atomicAdd(op,     w * acc[mf][nf][0]);
                atomicAdd(op + 1, w * acc[mf][nf][1]);
            }
            int t1 = toks[r + 8];
            if (t1 >= 0) {
                float w = wgts[r + 8];
                float* op = out + (size_t)t1 * NH + h0 + c;
                atomicAdd(op,     w * acc[mf][nf][2]);
                atomicAdd(op + 1, w * acc[mf][nf][3]);
            }
        }
#undef G2_ISSUE
}

// ---------------- launch ----------------
extern "C" void kernel_launch(void* const* d_in, const int* in_sizes, int n_in,
                              void* d_out, int out_size) {
    const float* x  = (const float*)d_in[0];
    const float* gw = (const float*)d_in[1];
    const float* w1 = (const float*)d_in[2];
    const float* w2 = (const float*)d_in[3];
    const float* w3 = (const float*)d_in[4];
    float* out = (float*)d_out;

    static int configured = 0;
    if (!configured) {
        cudaFuncSetAttribute(k_gemm1, cudaFuncAttributeMaxDynamicSharedMemorySize, DSMEM);
        cudaFuncSetAttribute(k_gemm2, cudaFuncAttributeMaxDynamicSharedMemorySize, DSMEM);
        configured = 1;
    }

    k_prep<<<PREP_BLOCKS, 256>>>(x, gw, w1, w3, out);
    k_finalize<<<1, 256>>>();
    k_gemm1<<<dim3(MAX_TILES, 72), 256, DSMEM>>>(w1, w3, w2, 0);  // + w1/w3 upper cvt
    k_gemm1<<<dim3(MAX_TILES, 72), 256, DSMEM>>>(w1, w3, w2, 1);  // + w2 cvt
    k_gemm2<<<dim3(MAX_TILES, NH / 128), 256, DSMEM>>>(out);
}

// round 16
// speedup vs baseline: 1.1112x; 1.0042x over previous
#include <cuda_runtime.h>
#include <cuda_fp16.h>
#include <math.h>
#include <stdint.h>

// ---------------- problem constants ----------------
#define NT 4096
#define NH 2048
#define NF 8192
#define NE 8

#define BM 128
#define KB 64                           // K halves per stage (128B rows)
#define NSLOT (2*NT)                    // 8192
#define MAX_TILES (NSLOT/BM + NE)       // 72
#define MAX_SLOTS (MAX_TILES*BM)        // 9216
#define NST1 (NH/KB)                    // 32
#define NST2 (NF/KB)                    // 128

// smem: toks/wgts in [0,1024); 3 stages x 32KB
#define TILE0   1024
#define SA      16384                   // A tile 128x64 fp16
#define SB1     8192                    // gemm1 B tile 64x64 fp16 (per matrix)
#define STRIDE  32768
#define DSMEM   (TILE0 + 3*STRIDE)      // 99328 -> 2 CTAs/SM

// ---------------- device scratch ----------------
__device__ int    g_tok_expert[NSLOT];
__device__ float  g_tok_weight[NSLOT];
__device__ int    g_slot_token[MAX_SLOTS];
__device__ float  g_slot_weight[MAX_SLOTS];
__device__ int    g_tile_expert[MAX_TILES];
__device__ __half g_hh[(size_t)MAX_SLOTS * NF];      // 151 MB
__device__ __half g_xh[(size_t)NT * NH];             // 16 MB
__device__ __half g_w1h[(size_t)NE * NF * NH];       // 268 MB
__device__ __half g_w3h[(size_t)NE * NF * NH];       // 268 MB
__device__ __half g_w2h[(size_t)NE * NH * NF];       // 268 MB

// ---------------- PTX helpers ----------------
__device__ __forceinline__ uint32_t s2u(const void* p) {
    uint32_t a;
    asm("{ .reg .u64 t; cvta.to.shared.u64 t, %1; cvt.u32.u64 %0, t; }" : "=r"(a) : "l"(p));
    return a;
}
#define CP16(dst, src, sz)                                                     \
    asm volatile("cp.async.cg.shared.global [%0], [%1], 16, %2;"               \
                 :: "r"(dst), "l"(src), "r"(sz))
#define CP_COMMIT() asm volatile("cp.async.commit_group;" ::: "memory")
#define CP_WAIT1()  asm volatile("cp.async.wait_group 1;" ::: "memory")

#define LDSM4(r, a)                                                            \
    asm volatile("ldmatrix.sync.aligned.m8n8.x4.shared.b16 {%0,%1,%2,%3}, [%4];" \
        : "=r"((r)[0]), "=r"((r)[1]), "=r"((r)[2]), "=r"((r)[3]) : "r"(a))

__device__ __forceinline__ void mma16(float* d, const uint32_t* a, const uint32_t* b) {
    asm volatile(
        "mma.sync.aligned.m16n8k16.row.col.f32.f16.f16.f32 "
        "{%0,%1,%2,%3},{%4,%5,%6,%7},{%8,%9},{%0,%1,%2,%3};"
        : "+f"(d[0]), "+f"(d[1]), "+f"(d[2]), "+f"(d[3])
        : "r"(a[0]), "r"(a[1]), "r"(a[2]), "r"(a[3]), "r"(b[0]), "r"(b[1]));
}

__device__ __forceinline__ void cvt_store(const float4* src, __half2* dst, size_t i) {
    float4 v = src[i];
    dst[2 * i]     = __floats2half2_rn(v.x, v.y);
    dst[2 * i + 1] = __floats2half2_rn(v.z, v.w);
}

// ---------------- sizes ----------------
#define N4_OUT  ((size_t)NT * NH / 4)          // 2,097,152 float4
#define N4_W    ((size_t)NE * NF * NH / 4)     // 33,554,432 float4 (per weight)
#define HALF4   ((size_t)NF * NH / 8)          // 2,097,152 float4 (half expert)
#define N4_WH   (N4_W / 2)                     // 16,777,216 (lower/upper half)

// prep: zero + x cvt + w1/w3 LOWER halves; router interleaved every 37th block
#define PREP_BLOCKS 151552u

__global__ void k_prep(const float* __restrict__ x, const float* __restrict__ gw,
                       const float* __restrict__ w1, const float* __restrict__ w3,
                       float* __restrict__ out) {
    const int tid = threadIdx.x;
    const unsigned bx = blockIdx.x;

    if (bx % 37u == 0u) {                        // router block (t = bx/37 < 4096)
        const int t = (int)(bx / 37u);
        float acc[NE];
#pragma unroll
        for (int e = 0; e < NE; e++) acc[e] = 0.f;
        const float* xr = x + (size_t)t * NH;
        for (int h = tid; h < NH; h += 256) {
            float xv = xr[h];
#pragma unroll
            for (int e = 0; e < NE; e++) acc[e] += xv * gw[e * NH + h];
        }
        __shared__ float part[NE][256];
#pragma unroll
        for (int e = 0; e < NE; e++) part[e][tid] = acc[e];
        __syncthreads();
        if (tid < NE) {
            float s = 0.f;
            for (int i = 0; i < 256; i++) s += part[tid][i];
            part[tid][0] = s;
        }
        __syncthreads();
        if (tid == 0) {
            float l[NE];
#pragma unroll
            for (int e = 0; e < NE; e++) l[e] = part[e][0];
            int i0 = 0;
#pragma unroll
            for (int e = 1; e < NE; e++) if (l[e] > l[i0]) i0 = e;
            int i1 = -1;
#pragma unroll
            for (int e = 0; e < NE; e++)
                if (e != i0 && (i1 < 0 || l[e] > l[i1])) i1 = e;
            float w0 = 1.f / (1.f + expf(l[i1] - l[i0]));
            g_tok_expert[2 * t] = i0;  g_tok_expert[2 * t + 1] = i1;
            g_tok_weight[2 * t] = w0;  g_tok_weight[2 * t + 1] = 1.f - w0;
        }
        return;
    }

    const unsigned bulk = bx - (bx / 37u) - 1u;
    size_t i = (size_t)bulk * 256 + tid;
    if (i < N4_OUT) {
        ((float4*)out)[i] = make_float4(0.f, 0.f, 0.f, 0.f);
        return;
    }
    i -= N4_OUT;
    if (i < N4_OUT) { cvt_store((const float4*)x, (__half2*)g_xh, i); return; }
    i -= N4_OUT;
    if (i < N4_WH) {                             // w1 lower half (per expert)
        size_t e = i >> 21, off = i & (HALF4 - 1);
        size_t idx = (e << 22) + off;
        cvt_store((const float4*)w1, (__half2*)g_w1h, idx);
        return;
    }
    i -= N4_WH;
    if (i < N4_WH) {                             // w3 lower half
        size_t e = i >> 21, off = i & (HALF4 - 1);
        size_t idx = (e << 22) + off;
        cvt_store((const float4*)w3, (__half2*)g_w3h, idx);
    }
}

// ---------------- finalize: counts -> offsets -> tile map -> slots ----------------
__global__ void k_finalize() {
    const int tid = threadIdx.x;
    __shared__ int cnt[NE], off[NE + 1], cur[NE];
    if (tid < NE) { cnt[tid] = 0; cur[tid] = 0; }
    __syncthreads();
    for (int i = tid; i < NSLOT; i += 256) atomicAdd(&cnt[g_tok_expert[i]], 1);
    __syncthreads();
    if (tid == 0) {
        int o = 0;
        for (int e = 0; e < NE; e++) {
            off[e] = o;
            o += ((cnt[e] + BM - 1) / BM) * BM;
        }
        off[NE] = o;
    }
    __syncthreads();
    const int ntiles = off[NE] / BM;
    for (int i = tid; i < MAX_TILES; i += 256) {
        int ex = -1;
        if (i < ntiles) {
            int r = i * BM;
            for (int e = 0; e < NE; e++)
                if (r >= off[e] && r < off[e + 1]) ex = e;
        }
        g_tile_expert[i] = ex;
    }
    for (int i = tid; i < MAX_SLOTS; i += 256) {
        g_slot_token[i]  = -1;
        g_slot_weight[i] = 0.f;
    }
    __syncthreads();
    for (int i = tid; i < NSLOT; i += 256) {
        int e = g_tok_expert[i];
        int pos = atomicAdd(&cur[e], 1);
        int s = off[e] + pos;
        g_slot_token[s]  = i >> 1;
        g_slot_weight[s] = g_tok_weight[i];
    }
}

// ---------------- GEMM1, launched twice with fhalf = 0 / 1 ----------------
// grid (x=72, y=72). y%9==8 -> cvt slice (fhalf0: w1/w3 upper; fhalf1: w2).
__global__ void __launch_bounds__(256, 2)
k_gemm1(const float* __restrict__ w1src, const float* __restrict__ w3src,
        const float* __restrict__ w2src, int fhalf) {
    const int tid = threadIdx.x;
    const int y = blockIdx.y;

    if (y % 9 == 8) {
        const size_t lin   = ((size_t)(y / 9) * MAX_TILES + blockIdx.x) * 256 + tid;
        const size_t strid = (size_t)8 * MAX_TILES * 256;        // 147,456
        if (fhalf == 0) {
            for (size_t j = lin; j < N4_WH; j += strid) {
                size_t e = j >> 21, off = j & (HALF4 - 1);
                size_t idx = (e << 22) + HALF4 + off;            // upper half
                cvt_store((const float4*)w1src, (__half2*)g_w1h, idx);
                cvt_store((const float4*)w3src, (__half2*)g_w3h, idx);
            }
        } else {
            for (size_t j = lin; j < N4_W; j += strid)
                cvt_store((const float4*)w2src, (__half2*)g_w2h, j);
        }
        return;
    }

    const int e = g_tile_expert[blockIdx.x];
    if (e < 0) return;
    extern __shared__ char smem[];
    const uint32_t sb = s2u(smem);
    const int lane = tid & 31, wid = tid >> 5;
    const int fblk = fhalf * 64 + (y - y / 9);        // 0..127
    const int r0 = blockIdx.x * BM, f0 = fblk * 64;

    int* toks = (int*)smem;
    if (tid < BM) toks[tid] = g_slot_token[r0 + tid];
    __syncthreads();

    const __half* srcA[4]; uint32_t dstA[4], szA[4];
    const __half* srcB1[2]; const __half* srcB3[2]; uint32_t dstB[2];
#pragma unroll
    for (int i = 0; i < 4; i++) {
        int idx = tid + 256 * i, row = idx >> 3, q = idx & 7;
        int t = toks[row];
        szA[i]  = (t >= 0) ? 16u : 0u;
        srcA[i] = g_xh + (size_t)(t >= 0 ? t : 0) * NH + q * 8;
        dstA[i] = sb + TILE0 + row * 128 + ((q ^ (row & 7)) << 4);
    }
#pragma unroll
    for (int i = 0; i < 2; i++) {
        int idx = tid + 256 * i, row = idx >> 3, q = idx & 7;   // row 0..63
        srcB1[i] = g_w1h + ((size_t)e * NF + f0 + row) * NH + q * 8;
        srcB3[i] = g_w3h + ((size_t)e * NF + f0 + row) * NH + q * 8;
        dstB[i]  = sb + TILE0 + SA + row * 128 + ((q ^ (row & 7)) << 4);
    }

#define G1_ISSUE(S) do {                                                       \
        uint32_t _o = ((S) % 3) * STRIDE; int _k = (S) * KB;                   \
        _Pragma("unroll") for (int i = 0; i < 4; i++)                          \
            CP16(dstA[i] + _o, srcA[i] + _k, szA[i]);                          \
        _Pragma("unroll") for (int i = 0; i < 2; i++)                          \
            CP16(dstB[i] + _o, srcB1[i] + _k, 16u);                            \
        _Pragma("unroll") for (int i = 0; i < 2; i++)                          \
            CP16(dstB[i] + _o + SB1, srcB3[i] + _k, 16u);                      \
        CP_COMMIT();                                                           \
    } while (0)

    G1_ISSUE(0); G1_ISSUE(1);

    const int mat = wid >> 2, wm = (wid >> 1) & 1, wn = wid & 1;
    uint32_t mOff[4], nOff[2], swzA[4], swzB[4];
#pragma unroll
    for (int mf = 0; mf < 4; mf++) mOff[mf] = (wm * 64 + mf * 16 + (lane & 15)) * 128;
#pragma unroll
    for (int np = 0; np < 2; np++)
        nOff[np] = (wn * 32 + np * 16 + ((lane >> 4) << 3) + (lane & 7)) * 128;
#pragma unroll
    for (int ks = 0; ks < 4; ks++) {
        swzA[ks] = ((2 * ks + (lane >> 4)) ^ (lane & 7)) << 4;
        swzB[ks] = ((2 * ks + ((lane >> 3) & 1)) ^ (lane & 7)) << 4;
    }

    float acc[4][4][4] = {};

    // single barrier per stage: top sync of iter s guarantees all warps
    // finished compute(s-1), making ISSUE(s+2)'s write to buffer (s-1)%3 safe.
    for (int s = 0; s < NST1; s++) {
        CP_WAIT1();
        __syncthreads();
        if (s + 2 < NST1) G1_ISSUE(s + 2); else CP_COMMIT();
        const uint32_t aB = sb + TILE0 + (s % 3) * STRIDE;
        const uint32_t bB = aB + SA + mat * SB1;
#pragma unroll
        for (int ks = 0; ks < 4; ks++) {
            uint32_t a[4][4], b[2][4];
#pragma unroll
            for (int mf = 0; mf < 4; mf++) LDSM4(a[mf], aB + mOff[mf] + swzA[ks]);
#pragma unroll
            for (int np = 0; np < 2; np++) LDSM4(b[np], bB + nOff[np] + swzB[ks]);
#pragma unroll
            for (int mf = 0; mf < 4; mf++)
#pragma unroll
                for (int nf = 0; nf < 4; nf++)
                    mma16(acc[mf][nf], a[mf], &b[nf >> 1][(nf & 1) * 2]);
        }
    }
    __syncthreads();   // all MMA smem reads done before epilogue overwrites buffers

    float* Sg = (float*)(smem + TILE0 + mat * 32768);
    const int rb = wm * 64, cb = wn * 32;
#pragma unroll
    for (int mf = 0; mf < 4; mf++)
#pragma unroll
        for (int nf = 0; nf < 4; nf++) {
            int r = rb + mf * 16 + (lane >> 2), c = cb + nf * 8 + (lane & 3) * 2;
            Sg[r * 64 + c]           = acc[mf][nf][0];
            Sg[r * 64 + c + 1]       = acc[mf][nf][1];
            Sg[(r + 8) * 64 + c]     = acc[mf][nf][2];
            Sg[(r + 8) * 64 + c + 1] = acc[mf][nf][3];
        }
    __syncthreads();
    const float4* S1 = (const float4*)(smem + TILE0);
    const float4* S3 = (const float4*)(smem + TILE0 + 32768);
#pragma unroll
    for (int k2 = 0; k2 < 8; k2++) {
        int i4 = tid + 256 * k2;
        int row = i4 >> 4, c4 = i4 & 15;
        float4 a = S1[i4], g = S3[i4];
        __half2 lo = __floats2half2_rn(a.x / (1.f + __expf(-a.x)) * g.x,
                                       a.y / (1.f + __expf(-a.y)) * g.y);
        __half2 hi = __floats2half2_rn(a.z / (1.f + __expf(-a.z)) * g.z,
                                       a.w / (1.f + __expf(-a.w)) * g.w);
        __half2* hp = (__half2*)(g_hh + (size_t)(r0 + row) * NF + f0 + c4 * 4);
        hp[0] = lo; hp[1] = hi;
    }
#undef G1_ISSUE
}

// ---------------- GEMM2: tile 128 x 128, 2 CTAs/SM ----------------
__global__ void __launch_bounds__(256, 2)
k_gemm2(float* __restrict__ out) {
    const int e = g_tile_expert[blockIdx.x];
    if (e < 0) return;
    extern __shared__ char smem[];
    const uint32_t sb = s2u(smem);
    const int tid = threadIdx.x, lane = tid & 31, wid = tid >> 5;
    const int r0 = blockIdx.x * BM, h0 = blockIdx.y * 128;

    int*   toks = (int*)smem;
    float* wgts = (float*)(smem + 512);
    if (tid < BM) {
        toks[tid] = g_slot_token[r0 + tid];
        wgts[tid] = g_slot_weight[r0 + tid];
    }
    __syncthreads();

    const __half* srcA[4]; uint32_t dstA[4];
    const __half* srcB[4]; uint32_t dstB[4];
#pragma unroll
    for (int i = 0; i < 4; i++) {
        int idx = tid + 256 * i, row = idx >> 3, q = idx & 7;
        srcA[i] = g_hh + (size_t)(r0 + row) * NF + q * 8;
        srcB[i] = g_w2h + ((size_t)e * NH + h0 + row) * NF + q * 8;
        uint32_t sw = row * 128 + ((q ^ (row & 7)) << 4);
        dstA[i] = sb + TILE0 + sw;
        dstB[i] = sb + TILE0 + SA + sw;
    }

#define G2_ISSUE(S) do {                                                       \
        uint32_t _o = ((S) % 3) * STRIDE; int _k = (S) * KB;                   \
        _Pragma("unroll") for (int i = 0; i < 4; i++)                          \
            CP16(dstA[i] + _o, srcA[i] + _k, 16u);                             \
        _Pragma("unroll") for (int i = 0; i < 4; i++)                          \
            CP16(dstB[i] + _o, srcB[i] + _k, 16u);                             \
        CP_COMMIT();                                                           \
    } while (0)

    G2_ISSUE(0); G2_ISSUE(1);

    const int wm = wid >> 2, wn = wid & 3;
    uint32_t mOff[4], nOff[2], swzA[4], swzB[4];
#pragma unroll
    for (int mf = 0; mf < 4; mf++) mOff[mf] = (wm * 64 + mf * 16 + (lane & 15)) * 128;
#pragma unroll
    for (int np = 0; np < 2; np++)
        nOff[np] = (wn * 32 + np * 16 + ((lane >> 4) << 3) + (lane & 7)) * 128;
#pragma unroll
    for (int ks = 0; ks < 4; ks++) {
        swzA[ks] = ((2 * ks + (lane >> 4)) ^ (lane & 7)) << 4;
        swzB[ks] = ((2 * ks + ((lane >> 3) & 1)) ^ (lane & 7)) << 4;
    }

    float acc[4][4][4] = {};

    for (int s = 0; s < NST2; s++) {
        CP_WAIT1();
        __syncthreads();
        if (s + 2 < NST2) G2_ISSUE(s + 2); else CP_COMMIT();
        const uint32_t aB = sb + TILE0 + (s % 3) * STRIDE;
        const uint32_t bB = aB + SA;
#pragma unroll
        for (int ks = 0; ks < 4; ks++) {
            uint32_t a[4][4], b[2][4];
#pragma unroll
            for (int mf = 0; mf < 4; mf++) LDSM4(a[mf], aB + mOff[mf] + swzA[ks]);
#pragma unroll
            for (int np = 0; np < 2; np++) LDSM4(b[np], bB + nOff[np] + swzB[ks]);
#pragma unroll
            for (int mf = 0; mf < 4; mf++)
#pragma unroll
                for (int nf = 0; nf < 4; nf++)
                    mma16(acc[mf][nf], a[mf], &b[nf >> 1][(nf & 1) * 2]);
        }
    }

    const int rb = wm * 64, cb = wn * 32;
#pragma unroll
    for (int mf = 0; mf < 4; mf++)
#pragma unroll
        for (int nf = 0; nf < 4; nf++) {
            int r = rb + mf * 16 + (lane >> 2), c = cb + nf * 8 + (lane & 3) * 2;
            int t0 = toks[r];
            if (t0 >= 0) {
                float w = wgts[r];
                float* op = out + (size_t)t0 * NH + h0 + c;
                atomicAdd(op,     w * acc[mf][nf][0]);
                atomicAdd(op + 1, w * acc[mf][nf][1]);
            }
            int t1 = toks[r + 8];
            if (t1 >= 0) {
                float w = wgts[r + 8];
                float* op = out + (size_t)t1 * NH + h0 + c;
                atomicAdd(op,     w * acc[mf][nf][2]);
                atomicAdd(op + 1, w * acc[mf][nf][3]);
            }
        }
#undef G2_ISSUE
}

// ---------------- launch ----------------
extern "C" void kernel_launch(void* const* d_in, const int* in_sizes, int n_in,
                              void* d_out, int out_size) {
    const float* x  = (const float*)d_in[0];
    const float* gw = (const float*)d_in[1];
    const float* w1 = (const float*)d_in[2];
    const float* w2 = (const float*)d_in[3];
    const float* w3 = (const float*)d_in[4];
    float* out = (float*)d_out;

    static int configured = 0;
    if (!configured) {
        cudaFuncSetAttribute(k_gemm1, cudaFuncAttributeMaxDynamicSharedMemorySize, DSMEM);
        cudaFuncSetAttribute(k_gemm2, cudaFuncAttributeMaxDynamicSharedMemorySize, DSMEM);
        configured = 1;
    }

    k_prep<<<PREP_BLOCKS, 256>>>(x, gw, w1, w3, out);
    k_finalize<<<1, 256>>>();
    k_gemm1<<<dim3(MAX_TILES, 72), 256, DSMEM>>>(w1, w3, w2, 0);  // + w1/w3 upper cvt
    k_gemm1<<<dim3(MAX_TILES, 72), 256, DSMEM>>>(w1, w3, w2, 1);  // + w2 cvt
    k_gemm2<<<dim3(MAX_TILES, NH / 128), 256, DSMEM>>>(out);
}

// round 17
// speedup vs baseline: 1.1123x; 1.0010x over previous
#include <cuda_runtime.h>
#include <cuda_fp16.h>
#include <math.h>
#include <stdint.h>

// ---------------- problem constants ----------------
#define NT 4096
#define NH 2048
#define NF 8192
#define NE 8

#define BM 128
#define KB 64                           // K halves per stage (128B rows)
#define NSLOT (2*NT)                    // 8192
#define MAX_TILES (NSLOT/BM + NE)       // 72
#define MAX_SLOTS (MAX_TILES*BM)        // 9216
#define NST1 (NH/KB)                    // 32
#define NST2 (NF/KB)                    // 128

// smem: toks/wgts in [0,1024); 3 stages x 32KB
#define TILE0   1024
#define SA      16384                   // A tile 128x64 fp16
#define SB1     8192                    // gemm1 B tile 64x64 fp16 (per matrix)
#define STRIDE  32768
#define DSMEM   (TILE0 + 3*STRIDE)      // 99328 -> 2 CTAs/SM

// ---------------- device scratch ----------------
__device__ int    g_tok_expert[NSLOT];
__device__ float  g_tok_weight[NSLOT];
__device__ int    g_slot_token[MAX_SLOTS];
__device__ float  g_slot_weight[MAX_SLOTS];
__device__ int    g_tile_expert[MAX_TILES];
__device__ __half g_hh[(size_t)MAX_SLOTS * NF];      // 151 MB
__device__ __half g_xh[(size_t)NT * NH];             // 16 MB
__device__ __half g_w1h[(size_t)NE * NF * NH];       // 268 MB
__device__ __half g_w3h[(size_t)NE * NF * NH];       // 268 MB
__device__ __half g_w2h[(size_t)NE * NH * NF];       // 268 MB

// ---------------- PTX helpers ----------------
__device__ __forceinline__ uint32_t s2u(const void* p) {
    uint32_t a;
    asm("{ .reg .u64 t; cvta.to.shared.u64 t, %1; cvt.u32.u64 %0, t; }" : "=r"(a) : "l"(p));
    return a;
}
#define CP16(dst, src, sz)                                                     \
    asm volatile("cp.async.cg.shared.global [%0], [%1], 16, %2;"               \
                 :: "r"(dst), "l"(src), "r"(sz))
#define CP_COMMIT() asm volatile("cp.async.commit_group;" ::: "memory")
#define CP_WAIT1()  asm volatile("cp.async.wait_group 1;" ::: "memory")

#define LDSM4(r, a)                                                            \
    asm volatile("ldmatrix.sync.aligned.m8n8.x4.shared.b16 {%0,%1,%2,%3}, [%4];" \
        : "=r"((r)[0]), "=r"((r)[1]), "=r"((r)[2]), "=r"((r)[3]) : "r"(a))

__device__ __forceinline__ void mma16(float* d, const uint32_t* a, const uint32_t* b) {
    asm volatile(
        "mma.sync.aligned.m16n8k16.row.col.f32.f16.f16.f32 "
        "{%0,%1,%2,%3},{%4,%5,%6,%7},{%8,%9},{%0,%1,%2,%3};"
        : "+f"(d[0]), "+f"(d[1]), "+f"(d[2]), "+f"(d[3])
        : "r"(a[0]), "r"(a[1]), "r"(a[2]), "r"(a[3]), "r"(b[0]), "r"(b[1]));
}

__device__ __forceinline__ void cvt_store(const float4* src, __half2* dst, size_t i) {
    float4 v = src[i];
    dst[2 * i]     = __floats2half2_rn(v.x, v.y);
    dst[2 * i + 1] = __floats2half2_rn(v.z, v.w);
}

// ---------------- sizes ----------------
#define N4_OUT  ((size_t)NT * NH / 4)          // 2,097,152 float4
#define N4_W    ((size_t)NE * NF * NH / 4)     // 33,554,432 float4 (per weight)
#define HALF4   ((size_t)NF * NH / 8)          // 2,097,152 float4 (half expert)
#define N4_WH   (N4_W / 2)                     // 16,777,216 (lower/upper half)

// prep: zero + x cvt + w1/w3 LOWER halves; router interleaved every 37th block
#define PREP_BLOCKS 151552u

__global__ void k_prep(const float* __restrict__ x, const float* __restrict__ gw,
                       const float* __restrict__ w1, const float* __restrict__ w3,
                       float* __restrict__ out) {
    const int tid = threadIdx.x;
    const unsigned bx = blockIdx.x;

    if (bx % 37u == 0u) {                        // router block (t = bx/37 < 4096)
        const int t = (int)(bx / 37u);
        float acc[NE];
#pragma unroll
        for (int e = 0; e < NE; e++) acc[e] = 0.f;
        const float* xr = x + (size_t)t * NH;
        for (int h = tid; h < NH; h += 256) {
            float xv = xr[h];
#pragma unroll
            for (int e = 0; e < NE; e++) acc[e] += xv * gw[e * NH + h];
        }
        __shared__ float part[NE][256];
#pragma unroll
        for (int e = 0; e < NE; e++) part[e][tid] = acc[e];
        __syncthreads();
        if (tid < NE) {
            float s = 0.f;
            for (int i = 0; i < 256; i++) s += part[tid][i];
            part[tid][0] = s;
        }
        __syncthreads();
        if (tid == 0) {
            float l[NE];
#pragma unroll
            for (int e = 0; e < NE; e++) l[e] = part[e][0];
            int i0 = 0;
#pragma unroll
            for (int e = 1; e < NE; e++) if (l[e] > l[i0]) i0 = e;
            int i1 = -1;
#pragma unroll
            for (int e = 0; e < NE; e++)
                if (e != i0 && (i1 < 0 || l[e] > l[i1])) i1 = e;
            float w0 = 1.f / (1.f + expf(l[i1] - l[i0]));
            g_tok_expert[2 * t] = i0;  g_tok_expert[2 * t + 1] = i1;
            g_tok_weight[2 * t] = w0;  g_tok_weight[2 * t + 1] = 1.f - w0;
        }
        return;
    }

    const unsigned bulk = bx - (bx / 37u) - 1u;
    size_t i = (size_t)bulk * 256 + tid;
    if (i < N4_OUT) {
        ((float4*)out)[i] = make_float4(0.f, 0.f, 0.f, 0.f);
        return;
    }
    i -= N4_OUT;
    if (i < N4_OUT) { cvt_store((const float4*)x, (__half2*)g_xh, i); return; }
    i -= N4_OUT;
    if (i < N4_WH) {                             // w1 lower half (per expert)
        size_t e = i >> 21, off = i & (HALF4 - 1);
        size_t idx = (e << 22) + off;
        cvt_store((const float4*)w1, (__half2*)g_w1h, idx);
        return;
    }
    i -= N4_WH;
    if (i < N4_WH) {                             // w3 lower half
        size_t e = i >> 21, off = i & (HALF4 - 1);
        size_t idx = (e << 22) + off;
        cvt_store((const float4*)w3, (__half2*)g_w3h, idx);
    }
}

// ---------------- finalize: counts -> offsets -> tile map -> slots ----------------
__global__ void k_finalize() {
    const int tid = threadIdx.x;
    __shared__ int cnt[NE], off[NE + 1], cur[NE];
    if (tid < NE) { cnt[tid] = 0; cur[tid] = 0; }
    __syncthreads();
    for (int i = tid; i < NSLOT; i += 256) atomicAdd(&cnt[g_tok_expert[i]], 1);
    __syncthreads();
    if (tid == 0) {
        int o = 0;
        for (int e = 0; e < NE; e++) {
            off[e] = o;
            o += ((cnt[e] + BM - 1) / BM) * BM;
        }
        off[NE] = o;
    }
    __syncthreads();
    const int ntiles = off[NE] / BM;
    for (int i = tid; i < MAX_TILES; i += 256) {
        int ex = -1;
        if (i < ntiles) {
            int r = i * BM;
            for (int e = 0; e < NE; e++)
                if (r >= off[e] && r < off[e + 1]) ex = e;
        }
        g_tile_expert[i] = ex;
    }
    for (int i = tid; i < MAX_SLOTS; i += 256) {
        g_slot_token[i]  = -1;
        g_slot_weight[i] = 0.f;
    }
    __syncthreads();
    for (int i = tid; i < NSLOT; i += 256) {
        int e = g_tok_expert[i];
        int pos = atomicAdd(&cur[e], 1);
        int s = off[e] + pos;
        g_slot_token[s]  = i >> 1;
        g_slot_weight[s] = g_tok_weight[i];
    }
}

// ---------------- GEMM1: 128 threads, 4 warps, warp tile 64x64 ----------------
// grid (x=72, y=72). y%9==8 -> cvt slice (fhalf0: w1/w3 upper; fhalf1: w2).
// warps 0,1 -> W1; warps 2,3 -> W3; each warp: 64 M-rows x full 64 N.
__global__ void __launch_bounds__(128, 2)
k_gemm1(const float* __restrict__ w1src, const float* __restrict__ w3src,
        const float* __restrict__ w2src, int fhalf) {
    const int tid = threadIdx.x;
    const int y = blockIdx.y;

    if (y % 9 == 8) {
        const size_t lin   = ((size_t)(y / 9) * MAX_TILES + blockIdx.x) * 128 + tid;
        const size_t strid = (size_t)8 * MAX_TILES * 128;        // 73,728
        if (fhalf == 0) {
            for (size_t j = lin; j < N4_WH; j += strid) {
                size_t e = j >> 21, off = j & (HALF4 - 1);
                size_t idx = (e << 22) + HALF4 + off;            // upper half
                cvt_store((const float4*)w1src, (__half2*)g_w1h, idx);
                cvt_store((const float4*)w3src, (__half2*)g_w3h, idx);
            }
        } else {
            for (size_t j = lin; j < N4_W; j += strid)
                cvt_store((const float4*)w2src, (__half2*)g_w2h, j);
        }
        return;
    }

    const int e = g_tile_expert[blockIdx.x];
    if (e < 0) return;
    extern __shared__ char smem[];
    const uint32_t sb = s2u(smem);
    const int lane = tid & 31, wid = tid >> 5;
    const int fblk = fhalf * 64 + (y - y / 9);        // 0..127
    const int r0 = blockIdx.x * BM, f0 = fblk * 64;

    int* toks = (int*)smem;
    toks[tid] = g_slot_token[r0 + tid];
    __syncthreads();

    // loaders (128 threads): A 8 chunks/thr; B1,B3 4 chunks/thr
    const __half* srcA[8]; uint32_t dstA[8], szA[8];
    const __half* srcB1[4]; const __half* srcB3[4]; uint32_t dstB[4];
#pragma unroll
    for (int i = 0; i < 8; i++) {
        int idx = tid + 128 * i, row = idx >> 3, q = idx & 7;   // row 0..127
        int t = toks[row];
        szA[i]  = (t >= 0) ? 16u : 0u;
        srcA[i] = g_xh + (size_t)(t >= 0 ? t : 0) * NH + q * 8;
        dstA[i] = sb + TILE0 + row * 128 + ((q ^ (row & 7)) << 4);
    }
#pragma unroll
    for (int i = 0; i < 4; i++) {
        int idx = tid + 128 * i, row = idx >> 3, q = idx & 7;   // row 0..63
        srcB1[i] = g_w1h + ((size_t)e * NF + f0 + row) * NH + q * 8;
        srcB3[i] = g_w3h + ((size_t)e * NF + f0 + row) * NH + q * 8;
        dstB[i]  = sb + TILE0 + SA + row * 128 + ((q ^ (row & 7)) << 4);
    }

#define G1_ISSUE(S) do {                                                       \
        uint32_t _o = ((S) % 3) * STRIDE; int _k = (S) * KB;                   \
        _Pragma("unroll") for (int i = 0; i < 8; i++)                          \
            CP16(dstA[i] + _o, srcA[i] + _k, szA[i]);                          \
        _Pragma("unroll") for (int i = 0; i < 4; i++)                          \
            CP16(dstB[i] + _o, srcB1[i] + _k, 16u);                            \
        _Pragma("unroll") for (int i = 0; i < 4; i++)                          \
            CP16(dstB[i] + _o + SB1, srcB3[i] + _k, 16u);                      \
        CP_COMMIT();                                                           \
    } while (0)

    G1_ISSUE(0); G1_ISSUE(1);

    // warp mapping: mat = wid>>1 (W1/W3), wm = wid&1 (M half); full 64 N
    const int mat = wid >> 1, wm = wid & 1;
    uint32_t mOff[4], nOff[4], swzA[4], swzB[4];
#pragma unroll
    for (int mf = 0; mf < 4; mf++) mOff[mf] = (wm * 64 + mf * 16 + (lane & 15)) * 128;
#pragma unroll
    for (int np = 0; np < 4; np++)
        nOff[np] = (np * 16 + ((lane >> 4) << 3) + (lane & 7)) * 128;
#pragma unroll
    for (int ks = 0; ks < 4; ks++) {
        swzA[ks] = ((2 * ks + (lane >> 4)) ^ (lane & 7)) << 4;
        swzB[ks] = ((2 * ks + ((lane >> 3) & 1)) ^ (lane & 7)) << 4;
    }

    float acc[4][8][4] = {};

    for (int s = 0; s < NST1; s++) {
        CP_WAIT1();
        __syncthreads();
        if (s + 2 < NST1) G1_ISSUE(s + 2); else CP_COMMIT();
        const uint32_t aB = sb + TILE0 + (s % 3) * STRIDE;
        const uint32_t bB = aB + SA + mat * SB1;
#pragma unroll
        for (int ks = 0; ks < 4; ks++) {
            uint32_t a[4][4], b[4][4];
#pragma unroll
            for (int mf = 0; mf < 4; mf++) LDSM4(a[mf], aB + mOff[mf] + swzA[ks]);
#pragma unroll
            for (int np = 0; np < 4; np++) LDSM4(b[np], bB + nOff[np] + swzB[ks]);
#pragma unroll
            for (int mf = 0; mf < 4; mf++)
#pragma unroll
                for (int nf = 0; nf < 8; nf++)
                    mma16(acc[mf][nf], a[mf], &b[nf >> 1][(nf & 1) * 2]);
        }
    }
    __syncthreads();   // all MMA smem reads done before epilogue overwrites buffers

    // epilogue: plane 128x64 f32 per mat, SwiGLU fuse, fp16 store
    float* Sg = (float*)(smem + TILE0 + mat * 32768);
    const int rb = wm * 64;
#pragma unroll
    for (int mf = 0; mf < 4; mf++)
#pragma unroll
        for (int nf = 0; nf < 8; nf++) {
            int r = rb + mf * 16 + (lane >> 2), c = nf * 8 + (lane & 3) * 2;
            Sg[r * 64 + c]           = acc[mf][nf][0];
            Sg[r * 64 + c + 1]       = acc[mf][nf][1];
            Sg[(r + 8) * 64 + c]     = acc[mf][nf][2];
            Sg[(r + 8) * 64 + c + 1] = acc[mf][nf][3];
        }
    __syncthreads();
    const float4* S1 = (const float4*)(smem + TILE0);
    const float4* S3 = (const float4*)(smem + TILE0 + 32768);
#pragma unroll
    for (int k2 = 0; k2 < 16; k2++) {
        int i4 = tid + 128 * k2;
        int row = i4 >> 4, c4 = i4 & 15;
        float4 a = S1[i4], g = S3[i4];
        __half2 lo = __floats2half2_rn(a.x / (1.f + __expf(-a.x)) * g.x,
                                       a.y / (1.f + __expf(-a.y)) * g.y);
        __half2 hi = __floats2half2_rn(a.z / (1.f + __expf(-a.z)) * g.z,
                                       a.w / (1.f + __expf(-a.w)) * g.w);
        __half2* hp = (__half2*)(g_hh + (size_t)(r0 + row) * NF + f0 + c4 * 4);
        hp[0] = lo; hp[1] = hi;
    }
#undef G1_ISSUE
}

// ---------------- GEMM2: 128 threads, 4 warps 2m x 2n, warp tile 64x64 ----------------
__global__ void __launch_bounds__(128, 2)
k_gemm2(float* __restrict__ out) {
    const int e = g_tile_expert[blockIdx.x];
    if (e < 0) return;
    extern __shared__ char smem[];
    const uint32_t sb = s2u(smem);
    const int tid = threadIdx.x, lane = tid & 31, wid = tid >> 5;
    const int r0 = blockIdx.x * BM, h0 = blockIdx.y * 128;

    int*   toks = (int*)smem;
    float* wgts = (float*)(smem + 512);
    toks[tid] = g_slot_token[r0 + tid];
    wgts[tid] = g_slot_weight[r0 + tid];
    __syncthreads();

    const __half* srcA[8]; uint32_t dstA[8];
    const __half* srcB[8]; uint32_t dstB[8];
#pragma unroll
    for (int i = 0; i < 8; i++) {
        int idx = tid + 128 * i, row = idx >> 3, q = idx & 7;   // row 0..127
        srcA[i] = g_hh + (size_t)(r0 + row) * NF + q * 8;
        srcB[i] = g_w2h + ((size_t)e * NH + h0 + row) * NF + q * 8;
        uint32_t sw = row * 128 + ((q ^ (row & 7)) << 4);
        dstA[i] = sb + TILE0 + sw;
        dstB[i] = sb + TILE0 + SA + sw;
    }

#define G2_ISSUE(S) do {                                                       \
        uint32_t _o = ((S) % 3) * STRIDE; int _k = (S) * KB;                   \
        _Pragma("unroll") for (int i = 0; i < 8; i++)                          \
            CP16(dstA[i] + _o, srcA[i] + _k, 16u);                             \
        _Pragma("unroll") for (int i = 0; i < 8; i++)                          \
            CP16(dstB[i] + _o, srcB[i] + _k, 16u);                             \
        CP_COMMIT();                                                           \
    } while (0)

    G2_ISSUE(0); G2_ISSUE(1);

    const int wm = wid >> 1, wn = wid & 1;
    uint32_t mOff[4], nOff[4], swzA[4], swzB[4];
#pragma unroll
    for (int mf = 0; mf < 4; mf++) mOff[mf] = (wm * 64 + mf * 16 + (lane & 15)) * 128;
#pragma unroll
    for (int np = 0; np < 4; np++)
        nOff[np] = (wn * 64 + np * 16 + ((lane >> 4) << 3) + (lane & 7)) * 128;
#pragma unroll
    for (int ks = 0; ks < 4; ks++) {
        swzA[ks] = ((2 * ks + (lane >> 4)) ^ (lane & 7)) << 4;
        swzB[ks] = ((2 * ks + ((lane >> 3) & 1)) ^ (lane & 7)) << 4;
    }

    float acc[4][8][4] = {};

    for (int s = 0; s < NST2; s++) {
        CP_WAIT1();
        __syncthreads();
        if (s + 2 < NST2) G2_ISSUE(s + 2); else CP_COMMIT();
        const uint32_t aB = sb + TILE0 + (s % 3) * STRIDE;
        const uint32_t bB = aB + SA;
#pragma unroll
        for (int ks = 0; ks < 4; ks++) {
            uint32_t a[4][4], b[4][4];
#pragma unroll
            for (int mf = 0; mf < 4; mf++) LDSM4(a[mf], aB + mOff[mf] + swzA[ks]);
#pragma unroll
            for (int np = 0; np < 4; np++) LDSM4(b[np], bB + nOff[np] + swzB[ks]);
#pragma unroll
            for (int mf = 0; mf < 4; mf++)
#pragma unroll
                for (int nf = 0; nf < 8; nf++)
                    mma16(acc[mf][nf], a[mf], &b[nf >> 1][(nf & 1) * 2]);
        }
    }

    // epilogue: weighted scatter-add (exactly 2 adds/elem -> deterministic)
    const int rb = wm * 64, cb = wn * 64;
#pragma unroll
    for (int mf = 0; mf < 4; mf++)
#pragma unroll
        for (int nf = 0; nf < 8; nf++) {
            int r = rb + mf * 16 + (lane >> 2), c = cb + nf * 8 + (lane & 3) * 2;
            int t0 = toks[r];
            if (t0 >= 0) {
                float w = wgts[r];
                float* op = out + (size_t)t0 * NH + h0 + c;
                atomicAdd(op,     w * acc[mf][nf][0]);
                atomicAdd(op + 1, w * acc[mf][nf][1]);
            }
            int t1 = toks[r + 8];
            if (t1 >= 0) {
                float w = wgts[r + 8];
                float* op = out + (size_t)t1 * NH + h0 + c;
                atomicAdd(op,     w * acc[mf][nf][2]);
                atomicAdd(op + 1, w * acc[mf][nf][3]);
            }
        }
#undef G2_ISSUE
}

// ---------------- launch ----------------
extern "C" void kernel_launch(void* const* d_in, const int* in_sizes, int n_in,
                              void* d_out, int out_size) {
    const float* x  = (const float*)d_in[0];
    const float* gw = (const float*)d_in[1];
    const float* w1 = (const float*)d_in[2];
    const float* w2 = (const float*)d_in[3];
    const float* w3 = (const float*)d_in[4];
    float* out = (float*)d_out;

    static int configured = 0;
    if (!configured) {
        cudaFuncSetAttribute(k_gemm1, cudaFuncAttributeMaxDynamicSharedMemorySize, DSMEM);
        cudaFuncSetAttribute(k_gemm2, cudaFuncAttributeMaxDynamicSharedMemorySize, DSMEM);
        configured = 1;
    }

    k_prep<<<PREP_BLOCKS, 256>>>(x, gw, w1, w3, out);
    k_finalize<<<1, 256>>>();
    k_gemm1<<<dim3(MAX_TILES, 72), 128, DSMEM>>>(w1, w3, w2, 0);  // + w1/w3 upper cvt
    k_gemm1<<<dim3(MAX_TILES, 72), 128, DSMEM>>>(w1, w3, w2, 1);  // + w2 cvt
    k_gemm2<<<dim3(MAX_TILES, NH / 128), 128, DSMEM>>>(out);
}